// round 4
// baseline (speedup 1.0000x reference)
#include <cuda_runtime.h>
#include <cstdint>

#define T     4096
#define E     300
#define HID   512
#define H2    256
#define KTAG  32
#define START_TAG 30
#define STOP_TAG  31
#define NEGV  -10000.0f

// ---------------- scratch (static __device__, no allocations) ----------------
__device__ float g_xg[T * E];              // gathered embeddings
__device__ float g_zx[2][T * 1024];        // Wih@x + b, permuted per-cluster layout
__device__ float g_hs[2][T * H2];          // h sequences
__device__ float g_feats[T * KTAG];        // emission features

// ---------------- helpers ----------------
__device__ __forceinline__ unsigned smem_u32(const void* p) {
    return (unsigned)__cvta_generic_to_shared(p);
}
__device__ __forceinline__ unsigned long long ffma2(unsigned long long a,
                                                    unsigned long long b,
                                                    unsigned long long c) {
    unsigned long long d;
    asm("fma.rn.f32x2 %0, %1, %2, %3;" : "=l"(d) : "l"(a), "l"(b), "l"(c));
    return d;
}
__device__ __forceinline__ float2 ull2f2(unsigned long long v) {
    float2 f;
    f.x = __uint_as_float((unsigned)(v & 0xffffffffull));
    f.y = __uint_as_float((unsigned)(v >> 32));
    return f;
}
__device__ __forceinline__ float sigf(float x) {
    return __fdividef(1.f, 1.f + __expf(-x));
}
__device__ __forceinline__ float tanhf_fast(float x) {
    return 1.f - __fdividef(2.f, 1.f + __expf(2.f * x));
}
__device__ __forceinline__ unsigned ordkey(float x) {
    unsigned b = __float_as_uint(x);
    return ((int)b) >= 0 ? (b | 0x80000000u) : ~b;
}
__device__ __forceinline__ void mbar_wait_cluster(unsigned mb, unsigned parity) {
    unsigned done;
    asm volatile(
        "{\n\t.reg .pred p;\n\t"
        "mbarrier.try_wait.parity.acquire.cluster.shared::cta.b64 p, [%1], %2;\n\t"
        "selp.b32 %0, 1, 0, p;\n\t}"
        : "=r"(done) : "r"(mb), "r"(parity) : "memory");
    while (!done) {
        asm volatile(
            "{\n\t.reg .pred p;\n\t"
            "mbarrier.try_wait.parity.acquire.cluster.shared::cta.b64 p, [%1], %2, 0x989680;\n\t"
            "selp.b32 %0, 1, 0, p;\n\t}"
            : "=r"(done) : "r"(mb), "r"(parity) : "memory");
    }
}

// ---------------- phase 0: embedding gather ----------------
__global__ void gather_kernel(const int* __restrict__ sent,
                              const float* __restrict__ embed) {
    int t = blockIdx.x;
    int row = sent[t];
    const float* src = embed + (size_t)row * E;
    for (int e = threadIdx.x; e < E; e += blockDim.x)
        g_xg[t * E + e] = src[e];
}

// ---------------- phase 1: input GEMM zx[dir][t][perm(r)] = Wih[r]·x[t]+b[r] ----------------
__global__ void gemm_zx_kernel(const float* __restrict__ Wf, const float* __restrict__ bf,
                               const float* __restrict__ Wb, const float* __restrict__ bb) {
    __shared__ float xs[32][33];
    __shared__ float ws[128][33];
    int dir = blockIdx.z;
    const float* W = dir ? Wb : Wf;
    const float* B = dir ? bb : bf;
    int t0 = blockIdx.x * 32, r0 = blockIdx.y * 128;
    int tid = threadIdx.x;
    int tq = tid & 7, rq = tid >> 3;

    float acc[4][4];
#pragma unroll
    for (int i = 0; i < 4; i++)
#pragma unroll
        for (int j = 0; j < 4; j++) acc[i][j] = 0.f;

    for (int k0 = 0; k0 < E; k0 += 32) {
        for (int idx = tid; idx < 32 * 32; idx += 256) {
            int tt = idx >> 5, e = idx & 31;
            int k = k0 + e;
            xs[tt][e] = (k < E) ? g_xg[(t0 + tt) * E + k] : 0.f;
        }
        for (int idx = tid; idx < 128 * 32; idx += 256) {
            int rr = idx >> 5, e = idx & 31;
            int k = k0 + e;
            ws[rr][e] = (k < E) ? W[(r0 + rr) * E + k] : 0.f;
        }
        __syncthreads();
#pragma unroll
        for (int e = 0; e < 32; e++) {
            float a[4], b4[4];
#pragma unroll
            for (int i = 0; i < 4; i++) a[i] = xs[4 * tq + i][e];
#pragma unroll
            for (int j = 0; j < 4; j++) b4[j] = ws[4 * rq + j][e];
#pragma unroll
            for (int i = 0; i < 4; i++)
#pragma unroll
                for (int j = 0; j < 4; j++) acc[i][j] = fmaf(a[i], b4[j], acc[i][j]);
        }
        __syncthreads();
    }
#pragma unroll
    for (int i = 0; i < 4; i++)
#pragma unroll
        for (int j = 0; j < 4; j++) {
            int t  = t0 + 4 * tq + i;
            int zr = r0 + 4 * rq + j;
            int g = zr >> 8, c = (zr >> 5) & 7, jj = zr & 31;
            int pos = c * 128 + g * 32 + jj;   // per-cluster-CTA contiguous layout
            g_zx[dir][t * 1024 + pos] = acc[i][j] + B[zr];
        }
}

// ---------------- phase 2: recurrent LSTM, cluster of 8 CTAs per direction ----------------
// Per step: in-warp q-reduction (shfl) + mbarrier handshake (no cluster.sync).
__global__ void __cluster_dims__(8, 1, 1) __launch_bounds__(256, 1)
lstm_kernel(const float* __restrict__ Whh_f, const float* __restrict__ Whh_b,
            const float* __restrict__ h0, const float* __restrict__ c0) {
    __shared__ __align__(16) float hbuf[2][H2];
    __shared__ __align__(16) float zbuf[128];
    __shared__ __align__(16) float hstage[32];
    __shared__ __align__(8) unsigned long long mbar[2];

    unsigned crank;
    asm("mov.u32 %0, %%cluster_ctarank;" : "=r"(crank));
    int dir = blockIdx.x >> 3;
    const float* Whh = dir ? Whh_b : Whh_f;
    int tid = threadIdx.x;
    int w = tid >> 5, l = tid & 31;
    int q = l >> 3, rp = l & 7;           // q = column group, interleaved chunks 4k+q
    int l0 = 16 * w + 2 * rp, l1 = l0 + 1; // local z-rows
    int zr0 = 256 * (l0 >> 5) + 32 * (int)crank + (l0 & 31);
    int zr1 = 256 * (l1 >> 5) + 32 * (int)crank + (l1 & 31);

    // Weights in registers: row zrX, columns = float4 chunks {4k+q}, k=0..15.
    unsigned long long wA[32], wB[32];
    {
        const ulonglong2* pa = reinterpret_cast<const ulonglong2*>(Whh + (size_t)zr0 * 256 + 4 * q);
        const ulonglong2* pb = reinterpret_cast<const ulonglong2*>(Whh + (size_t)zr1 * 256 + 4 * q);
#pragma unroll
        for (int k = 0; k < 16; k++) {
            ulonglong2 va = pa[4 * k];
            wA[2 * k] = va.x; wA[2 * k + 1] = va.y;
            ulonglong2 vb = pb[4 * k];
            wB[2 * k] = vb.x; wB[2 * k + 1] = vb.y;
        }
    }

    if (tid == 0) {
        asm volatile("mbarrier.init.shared.b64 [%0], %1;" :: "r"(smem_u32(&mbar[0])), "r"(32u) : "memory");
        asm volatile("mbarrier.init.shared.b64 [%0], %1;" :: "r"(smem_u32(&mbar[1])), "r"(32u) : "memory");
    }
    for (int i = tid; i < H2; i += 256) hbuf[0][i] = h0[dir * H2 + i];
    float creg = 0.f;
    if (tid < 32) creg = c0[dir * H2 + 32 * crank + tid];
    __syncthreads();
    asm volatile("barrier.cluster.arrive.aligned;" ::: "memory");
    asm volatile("barrier.cluster.wait.aligned;" ::: "memory");

    // zx for step 0 preloaded
    float zx0 = 0.f, zx1 = 0.f, zx2 = 0.f, zx3 = 0.f;
    if (tid < 32) {
        int t0i = dir ? (T - 1) : 0;
        const float* zp = &g_zx[dir][t0i * 1024 + (int)crank * 128 + tid];
        zx0 = zp[0]; zx1 = zp[32]; zx2 = zp[64]; zx3 = zp[96];
    }

#define LSTM_STEP(CUR, S, PAR)                                                       \
    {                                                                                \
        float zn0 = 0.f, zn1 = 0.f, zn2 = 0.f, zn3 = 0.f;                            \
        if (tid < 32 && (S) + 1 < T) {                                               \
            int tn = dir ? (T - 2 - (S)) : ((S) + 1);                                \
            const float* zp = &g_zx[dir][tn * 1024 + (int)crank * 128 + tid];        \
            zn0 = zp[0]; zn1 = zp[32]; zn2 = zp[64]; zn3 = zp[96];                   \
        }                                                                            \
        unsigned long long a0 = 0, a1 = 0, b0 = 0, b1 = 0;                           \
        const ulonglong2* hq = reinterpret_cast<const ulonglong2*>(hbuf[CUR]) + q;   \
        _Pragma("unroll")                                                            \
        for (int k = 0; k < 16; k++) {                                               \
            ulonglong2 h2 = hq[4 * k];                                               \
            a0 = ffma2(wA[2 * k],     h2.x, a0);                                     \
            a1 = ffma2(wA[2 * k + 1], h2.y, a1);                                     \
            b0 = ffma2(wB[2 * k],     h2.x, b0);                                     \
            b1 = ffma2(wB[2 * k + 1], h2.y, b1);                                     \
        }                                                                            \
        float2 fa0 = ull2f2(a0), fa1 = ull2f2(a1), fb0 = ull2f2(b0), fb1 = ull2f2(b1);\
        float sA = (fa0.x + fa0.y) + (fa1.x + fa1.y);                                \
        float sB = (fb0.x + fb0.y) + (fb1.x + fb1.y);                                \
        sA += __shfl_xor_sync(0xffffffffu, sA, 8);                                   \
        sB += __shfl_xor_sync(0xffffffffu, sB, 8);                                   \
        sA += __shfl_xor_sync(0xffffffffu, sA, 16);                                  \
        sB += __shfl_xor_sync(0xffffffffu, sB, 16);                                  \
        if (q == 0) { zbuf[l0] = sA; zbuf[l1] = sB; }                                \
        __syncthreads();                                                             \
        if (tid < 32) {                                                              \
            int t = dir ? (T - 1 - (S)) : (S);                                       \
            float zi = zbuf[tid]      + zx0;                                         \
            float zf = zbuf[32 + tid] + zx1;                                         \
            float zg = zbuf[64 + tid] + zx2;                                         \
            float zo = zbuf[96 + tid] + zx3;                                         \
            creg = sigf(zf) * creg + sigf(zi) * tanhf_fast(zg);                      \
            float hv = sigf(zo) * tanhf_fast(creg);                                  \
            hstage[tid] = hv;                                                        \
            g_hs[dir][t * H2 + 32 * (int)crank + tid] = hv;                          \
            __syncwarp();                                                            \
            int pr = tid >> 2, pp = tid & 3;                                         \
            float4 v0 = *reinterpret_cast<const float4*>(&hstage[8 * pp]);           \
            float4 v1 = *reinterpret_cast<const float4*>(&hstage[8 * pp + 4]);       \
            unsigned loff = smem_u32(&hbuf[(CUR) ^ 1][32 * (int)crank + 8 * pp]);    \
            unsigned moff = smem_u32(&mbar[(CUR) ^ 1]);                              \
            unsigned ra, rm;                                                         \
            asm("mapa.shared::cluster.u32 %0, %1, %2;" : "=r"(ra) : "r"(loff), "r"(pr)); \
            asm("mapa.shared::cluster.u32 %0, %1, %2;" : "=r"(rm) : "r"(moff), "r"(pr)); \
            asm volatile("st.shared::cluster.v4.f32 [%0], {%1,%2,%3,%4};"            \
                         :: "r"(ra), "f"(v0.x), "f"(v0.y), "f"(v0.z), "f"(v0.w) : "memory"); \
            asm volatile("st.shared::cluster.v4.f32 [%0], {%1,%2,%3,%4};"            \
                         :: "r"(ra + 16), "f"(v1.x), "f"(v1.y), "f"(v1.z), "f"(v1.w) : "memory"); \
            asm volatile("mbarrier.arrive.release.cluster.shared::cluster.b64 _, [%0];" \
                         :: "r"(rm) : "memory");                                     \
        }                                                                            \
        mbar_wait_cluster(smem_u32(&mbar[(CUR) ^ 1]), (unsigned)(PAR));              \
        zx0 = zn0; zx1 = zn1; zx2 = zn2; zx3 = zn3;                                  \
    }

    for (int i = 0; i < T / 2; i++) {
        int par = i & 1;
        LSTM_STEP(0, 2 * i,     par);   // read hbuf0 -> write hbuf1, wait mbar[1]
        LSTM_STEP(1, 2 * i + 1, par);   // read hbuf1 -> write hbuf0, wait mbar[0]
    }
#undef LSTM_STEP

    asm volatile("barrier.cluster.arrive.aligned;" ::: "memory");
    asm volatile("barrier.cluster.wait.aligned;" ::: "memory");
}

// ---------------- phase 3: emission features feats = [hf|hb] @ W_out^T + b_out ----------------
__global__ void feats_kernel(const float* __restrict__ Wout, const float* __restrict__ bout) {
    extern __shared__ float sm3[];
    float* wt  = sm3;              // [512][33] transposed, padded
    float* hsm = sm3 + HID * 33;   // [8][512]
    int tid = threadIdx.x;
    for (int idx = tid; idx < KTAG * HID; idx += 256) {
        int k = idx >> 9, d = idx & 511;
        wt[d * 33 + k] = Wout[idx];
    }
    int t0 = blockIdx.x * 8;
    for (int idx = tid; idx < 8 * HID; idx += 256) {
        int tt = idx >> 9, d = idx & 511;
        hsm[tt * HID + d] = (d < H2) ? g_hs[0][(t0 + tt) * H2 + d]
                                     : g_hs[1][(t0 + tt) * H2 + d - H2];
    }
    __syncthreads();
    int k = tid & 31, tt = tid >> 5;
    float acc = bout[k];
#pragma unroll 8
    for (int d = 0; d < HID; d++)
        acc = fmaf(hsm[tt * HID + d], wt[d * 33 + k], acc);
    g_feats[(t0 + tt) * KTAG + k] = acc;
}

// ---------------- phase 4: Viterbi forward + backtrace ----------------
__global__ void viterbi_kernel(const float* __restrict__ trans, float* __restrict__ out) {
    extern __shared__ char sm4[];
    unsigned char* bp = (unsigned char*)sm4;        // [T][32]
    float* fv = (float*)(sm4 + T * KTAG);           // [2][32]
    int tid = threadIdx.x, wid = tid >> 5, lane = tid & 31;
    float tr = trans[wid * KTAG + lane];
    if (tid < KTAG) fv[tid] = (tid == START_TAG) ? 0.f : NEGV;
    __syncthreads();

    int cur = 0;
    float feat = g_feats[wid];  // t = 0, row wid (broadcast load)
    for (int t = 0; t < T; t++) {
        float s = fv[cur * KTAG + lane] + tr;
        float fn = (t + 1 < T) ? g_feats[(t + 1) * KTAG + wid] : 0.f;  // prefetch
        unsigned key = ordkey(s);
        unsigned m   = __reduce_max_sync(0xffffffffu, key);
        unsigned bal = __ballot_sync(0xffffffffu, key == m);
        int js = __ffs(bal) - 1;                    // first index -> matches jnp.argmax
        if (lane == js) {
            fv[(cur ^ 1) * KTAG + wid] = s + feat;
            bp[t * KTAG + wid] = (unsigned char)js;
        }
        feat = fn;
        cur ^= 1;
        __syncthreads();
    }
    if (wid == 0) {
        float s = fv[cur * KTAG + lane] + trans[STOP_TAG * KTAG + lane];
        unsigned key = ordkey(s);
        unsigned m   = __reduce_max_sync(0xffffffffu, key);
        unsigned bal = __ballot_sync(0xffffffffu, key == m);
        int best = __ffs(bal) - 1;
        float ms = __shfl_sync(0xffffffffu, s, best);
        if (lane == 0) {
            out[0] = ms;
            int tag = best;
            for (int t = T - 1; t >= 0; --t) {
                out[1 + t] = (float)tag;
                tag = bp[t * KTAG + tag];
            }
        }
    }
}

// ---------------- launch ----------------
extern "C" void kernel_launch(void* const* d_in, const int* in_sizes, int n_in,
                              void* d_out, int out_size) {
    (void)in_sizes; (void)n_in; (void)out_size;
    const int*   sent  = (const int*)d_in[0];
    const float* embed = (const float*)d_in[1];
    const float* Wih_f = (const float*)d_in[2];
    const float* Whh_f = (const float*)d_in[3];
    const float* b_f   = (const float*)d_in[4];
    const float* Wih_b = (const float*)d_in[5];
    const float* Whh_b = (const float*)d_in[6];
    const float* b_b   = (const float*)d_in[7];
    const float* W_out = (const float*)d_in[8];
    const float* b_out = (const float*)d_in[9];
    const float* trans = (const float*)d_in[10];
    const float* h0    = (const float*)d_in[11];
    const float* c0    = (const float*)d_in[12];
    float* out = (float*)d_out;

    size_t fsm = (size_t)(HID * 33 + 8 * HID) * sizeof(float);          // ~84 KB
    size_t vsm = (size_t)(T * KTAG) + 2 * KTAG * sizeof(float) + 16;    // ~131.3 KB
    cudaFuncSetAttribute(feats_kernel,   cudaFuncAttributeMaxDynamicSharedMemorySize, (int)fsm);
    cudaFuncSetAttribute(viterbi_kernel, cudaFuncAttributeMaxDynamicSharedMemorySize, (int)vsm);

    gather_kernel<<<T, 128>>>(sent, embed);
    gemm_zx_kernel<<<dim3(T / 32, 8, 2), 256>>>(Wih_f, b_f, Wih_b, b_b);
    lstm_kernel<<<16, 256>>>(Whh_f, Whh_b, h0, c0);
    feats_kernel<<<T / 8, 256, fsm>>>(W_out, b_out);
    viterbi_kernel<<<1, 1024, vsm>>>(trans, out);
}

// round 6
// speedup vs baseline: 1.0811x; 1.0811x over previous
#include <cuda_runtime.h>
#include <cstdint>

#define T     4096
#define E     300
#define HID   512
#define H2    256
#define KTAG  32
#define START_TAG 30
#define STOP_TAG  31
#define NEGV  -10000.0f

// ---------------- scratch (static __device__, no allocations) ----------------
__device__ float g_xg[T * E];              // gathered embeddings
__device__ float g_zx[2][T * 1024];        // Wih@x + b, permuted per-cluster layout
__device__ float g_hs[2][T * H2];          // h sequences
__device__ float g_feats[T * KTAG];        // emission features

// ---------------- helpers ----------------
__device__ __forceinline__ unsigned smem_u32(const void* p) {
    return (unsigned)__cvta_generic_to_shared(p);
}
__device__ __forceinline__ unsigned long long ffma2(unsigned long long a,
                                                    unsigned long long b,
                                                    unsigned long long c) {
    unsigned long long d;
    asm("fma.rn.f32x2 %0, %1, %2, %3;" : "=l"(d) : "l"(a), "l"(b), "l"(c));
    return d;
}
__device__ __forceinline__ float2 ull2f2(unsigned long long v) {
    float2 f;
    f.x = __uint_as_float((unsigned)(v & 0xffffffffull));
    f.y = __uint_as_float((unsigned)(v >> 32));
    return f;
}
__device__ __forceinline__ float sigf(float x) {
    return __fdividef(1.f, 1.f + __expf(-x));
}
__device__ __forceinline__ float tanhf_fast(float x) {
    return 1.f - __fdividef(2.f, 1.f + __expf(2.f * x));
}
__device__ __forceinline__ unsigned ordkey(float x) {
    unsigned b = __float_as_uint(x);
    return ((int)b) >= 0 ? (b | 0x80000000u) : ~b;
}

// ---------------- phase 0: embedding gather ----------------
__global__ void gather_kernel(const int* __restrict__ sent,
                              const float* __restrict__ embed) {
    int t = blockIdx.x;
    int row = sent[t];
    const float* src = embed + (size_t)row * E;
    for (int e = threadIdx.x; e < E; e += blockDim.x)
        g_xg[t * E + e] = src[e];
}

// ---------------- phase 1: input GEMM zx[dir][t][perm(r)] = Wih[r]·x[t]+b[r] ----------------
__global__ void gemm_zx_kernel(const float* __restrict__ Wf, const float* __restrict__ bf,
                               const float* __restrict__ Wb, const float* __restrict__ bb) {
    __shared__ float xs[32][33];
    __shared__ float ws[128][33];
    int dir = blockIdx.z;
    const float* W = dir ? Wb : Wf;
    const float* B = dir ? bb : bf;
    int t0 = blockIdx.x * 32, r0 = blockIdx.y * 128;
    int tid = threadIdx.x;
    int tq = tid & 7, rq = tid >> 3;

    float acc[4][4];
#pragma unroll
    for (int i = 0; i < 4; i++)
#pragma unroll
        for (int j = 0; j < 4; j++) acc[i][j] = 0.f;

    for (int k0 = 0; k0 < E; k0 += 32) {
        for (int idx = tid; idx < 32 * 32; idx += 256) {
            int tt = idx >> 5, e = idx & 31;
            int k = k0 + e;
            xs[tt][e] = (k < E) ? g_xg[(t0 + tt) * E + k] : 0.f;
        }
        for (int idx = tid; idx < 128 * 32; idx += 256) {
            int rr = idx >> 5, e = idx & 31;
            int k = k0 + e;
            ws[rr][e] = (k < E) ? W[(r0 + rr) * E + k] : 0.f;
        }
        __syncthreads();
#pragma unroll
        for (int e = 0; e < 32; e++) {
            float a[4], b4[4];
#pragma unroll
            for (int i = 0; i < 4; i++) a[i] = xs[4 * tq + i][e];
#pragma unroll
            for (int j = 0; j < 4; j++) b4[j] = ws[4 * rq + j][e];
#pragma unroll
            for (int i = 0; i < 4; i++)
#pragma unroll
                for (int j = 0; j < 4; j++) acc[i][j] = fmaf(a[i], b4[j], acc[i][j]);
        }
        __syncthreads();
    }
#pragma unroll
    for (int i = 0; i < 4; i++)
#pragma unroll
        for (int j = 0; j < 4; j++) {
            int t  = t0 + 4 * tq + i;
            int zr = r0 + 4 * rq + j;
            int g = zr >> 8, c = (zr >> 5) & 7, jj = zr & 31;
            int pos = c * 128 + g * 32 + jj;   // per-cluster-CTA contiguous layout
            g_zx[dir][t * 1024 + pos] = acc[i][j] + B[zr];
        }
}

// ---------------- phase 2: recurrent LSTM, cluster of 8 CTAs per direction ----------------
// cluster.sync handshake (proven fast); in-warp shfl reduction; zx prefetch
// hidden between cluster.arrive and cluster.wait.
__global__ void __cluster_dims__(8, 1, 1) __launch_bounds__(256, 1)
lstm_kernel(const float* __restrict__ Whh_f, const float* __restrict__ Whh_b,
            const float* __restrict__ h0, const float* __restrict__ c0) {
    __shared__ __align__(16) float hbuf[2][H2];
    __shared__ __align__(16) float zbuf[128];
    __shared__ __align__(16) float hstage[32];

    unsigned crank;
    asm("mov.u32 %0, %%cluster_ctarank;" : "=r"(crank));
    int dir = blockIdx.x >> 3;
    const float* Whh = dir ? Whh_b : Whh_f;
    int tid = threadIdx.x;
    int w = tid >> 5, l = tid & 31;
    int q = l >> 3, rp = l & 7;             // q = column group; interleaved chunks 4k+q
    int l0 = 16 * w + 2 * rp, l1 = l0 + 1;  // local z-rows
    int zr0 = 256 * (l0 >> 5) + 32 * (int)crank + (l0 & 31);
    int zr1 = 256 * (l1 >> 5) + 32 * (int)crank + (l1 & 31);

    // Weights in registers: row zrX, columns = float4 chunks {4k+q}, k=0..15.
    unsigned long long wA[32], wB[32];
    {
        const ulonglong2* pa = reinterpret_cast<const ulonglong2*>(Whh + (size_t)zr0 * 256 + 4 * q);
        const ulonglong2* pb = reinterpret_cast<const ulonglong2*>(Whh + (size_t)zr1 * 256 + 4 * q);
#pragma unroll
        for (int k = 0; k < 16; k++) {
            ulonglong2 va = pa[4 * k];
            wA[2 * k] = va.x; wA[2 * k + 1] = va.y;
            ulonglong2 vb = pb[4 * k];
            wB[2 * k] = vb.x; wB[2 * k + 1] = vb.y;
        }
    }

    for (int i = tid; i < H2; i += 256) hbuf[0][i] = h0[dir * H2 + i];
    float creg = 0.f;
    if (tid < 32) creg = c0[dir * H2 + 32 * crank + tid];
    __syncthreads();
    asm volatile("barrier.cluster.arrive.aligned;" ::: "memory");
    asm volatile("barrier.cluster.wait.aligned;" ::: "memory");

    // zx for step 0 preloaded
    float zx0 = 0.f, zx1 = 0.f, zx2 = 0.f, zx3 = 0.f;
    if (tid < 32) {
        int t0i = dir ? (T - 1) : 0;
        const float* zp = &g_zx[dir][t0i * 1024 + (int)crank * 128 + tid];
        zx0 = zp[0]; zx1 = zp[32]; zx2 = zp[64]; zx3 = zp[96];
    }

#define LSTM_STEP(CUR, S)                                                            \
    {                                                                                \
        unsigned long long a0 = 0, a1 = 0, b0 = 0, b1 = 0;                           \
        const ulonglong2* hq = reinterpret_cast<const ulonglong2*>(hbuf[CUR]) + q;   \
        _Pragma("unroll")                                                            \
        for (int k = 0; k < 16; k++) {                                               \
            ulonglong2 h2 = hq[4 * k];                                               \
            a0 = ffma2(wA[2 * k],     h2.x, a0);                                     \
            a1 = ffma2(wA[2 * k + 1], h2.y, a1);                                     \
            b0 = ffma2(wB[2 * k],     h2.x, b0);                                     \
            b1 = ffma2(wB[2 * k + 1], h2.y, b1);                                     \
        }                                                                            \
        float2 fa0 = ull2f2(a0), fa1 = ull2f2(a1), fb0 = ull2f2(b0), fb1 = ull2f2(b1);\
        float sA = (fa0.x + fa0.y) + (fa1.x + fa1.y);                                \
        float sB = (fb0.x + fb0.y) + (fb1.x + fb1.y);                                \
        sA += __shfl_xor_sync(0xffffffffu, sA, 8);                                   \
        sB += __shfl_xor_sync(0xffffffffu, sB, 8);                                   \
        sA += __shfl_xor_sync(0xffffffffu, sA, 16);                                  \
        sB += __shfl_xor_sync(0xffffffffu, sB, 16);                                  \
        if (q == 0) { zbuf[l0] = sA; zbuf[l1] = sB; }                                \
        __syncthreads();                                                             \
        if (tid < 32) {                                                              \
            int t = dir ? (T - 1 - (S)) : (S);                                       \
            float zi = zbuf[tid]      + zx0;                                         \
            float zf = zbuf[32 + tid] + zx1;                                         \
            float zg = zbuf[64 + tid] + zx2;                                         \
            float zo = zbuf[96 + tid] + zx3;                                         \
            creg = sigf(zf) * creg + sigf(zi) * tanhf_fast(zg);                      \
            float hv = sigf(zo) * tanhf_fast(creg);                                  \
            hstage[tid] = hv;                                                        \
            g_hs[dir][t * H2 + 32 * (int)crank + tid] = hv;                          \
            __syncwarp();                                                            \
            int pr = tid >> 2, pp = tid & 3;                                         \
            float4 v0 = *reinterpret_cast<const float4*>(&hstage[8 * pp]);           \
            float4 v1 = *reinterpret_cast<const float4*>(&hstage[8 * pp + 4]);       \
            unsigned loff = smem_u32(&hbuf[(CUR) ^ 1][32 * (int)crank + 8 * pp]);    \
            unsigned ra;                                                             \
            asm("mapa.shared::cluster.u32 %0, %1, %2;" : "=r"(ra) : "r"(loff), "r"(pr)); \
            asm volatile("st.shared::cluster.v4.f32 [%0], {%1,%2,%3,%4};"            \
                         :: "r"(ra), "f"(v0.x), "f"(v0.y), "f"(v0.z), "f"(v0.w) : "memory"); \
            asm volatile("st.shared::cluster.v4.f32 [%0], {%1,%2,%3,%4};"            \
                         :: "r"(ra + 16), "f"(v1.x), "f"(v1.y), "f"(v1.z), "f"(v1.w) : "memory"); \
        }                                                                            \
        asm volatile("barrier.cluster.arrive.aligned;" ::: "memory");                \
        if (tid < 32 && (S) + 1 < T) {   /* prefetch hidden under barrier wait */    \
            int tn = dir ? (T - 2 - (S)) : ((S) + 1);                                \
            const float* zp = &g_zx[dir][tn * 1024 + (int)crank * 128 + tid];        \
            zx0 = zp[0]; zx1 = zp[32]; zx2 = zp[64]; zx3 = zp[96];                   \
        }                                                                            \
        asm volatile("barrier.cluster.wait.aligned;" ::: "memory");                  \
    }

    for (int i = 0; i < T / 2; i++) {
        LSTM_STEP(0, 2 * i);       // read hbuf0 -> write hbuf1
        LSTM_STEP(1, 2 * i + 1);   // read hbuf1 -> write hbuf0
    }
#undef LSTM_STEP

    asm volatile("barrier.cluster.arrive.aligned;" ::: "memory");
    asm volatile("barrier.cluster.wait.aligned;" ::: "memory");
}

// ---------------- phase 3: emission features feats = [hf|hb] @ W_out^T + b_out ----------------
__global__ void feats_kernel(const float* __restrict__ Wout, const float* __restrict__ bout) {
    extern __shared__ float sm3[];
    float* wt  = sm3;              // [512][33] transposed, padded
    float* hsm = sm3 + HID * 33;   // [8][512]
    int tid = threadIdx.x;
    for (int idx = tid; idx < KTAG * HID; idx += 256) {
        int k = idx >> 9, d = idx & 511;
        wt[d * 33 + k] = Wout[idx];
    }
    int t0 = blockIdx.x * 8;
    for (int idx = tid; idx < 8 * HID; idx += 256) {
        int tt = idx >> 9, d = idx & 511;
        hsm[tt * HID + d] = (d < H2) ? g_hs[0][(t0 + tt) * H2 + d]
                                     : g_hs[1][(t0 + tt) * H2 + d - H2];
    }
    __syncthreads();
    int k = tid & 31, tt = tid >> 5;
    float acc = bout[k];
#pragma unroll 8
    for (int d = 0; d < HID; d++)
        acc = fmaf(hsm[tt * HID + d], wt[d * 33 + k], acc);
    g_feats[(t0 + tt) * KTAG + k] = acc;
}

// ---------------- phase 4: Viterbi forward + backtrace ----------------
__global__ void viterbi_kernel(const float* __restrict__ trans, float* __restrict__ out) {
    extern __shared__ char sm4[];
    unsigned char* bp = (unsigned char*)sm4;        // [T][32]
    float* fv = (float*)(sm4 + T * KTAG);           // [2][32]
    int tid = threadIdx.x, wid = tid >> 5, lane = tid & 31;
    float tr = trans[wid * KTAG + lane];
    if (tid < KTAG) fv[tid] = (tid == START_TAG) ? 0.f : NEGV;
    __syncthreads();

    int cur = 0;
    float feat = g_feats[wid];  // t = 0, row wid (broadcast load)
    for (int t = 0; t < T; t++) {
        float s = fv[cur * KTAG + lane] + tr;
        float fn = (t + 1 < T) ? g_feats[(t + 1) * KTAG + wid] : 0.f;  // prefetch
        unsigned key = ordkey(s);
        unsigned m   = __reduce_max_sync(0xffffffffu, key);
        unsigned bal = __ballot_sync(0xffffffffu, key == m);
        int js = __ffs(bal) - 1;                    // first index -> matches jnp.argmax
        if (lane == js) {
            fv[(cur ^ 1) * KTAG + wid] = s + feat;
            bp[t * KTAG + wid] = (unsigned char)js;
        }
        feat = fn;
        cur ^= 1;
        __syncthreads();
    }
    if (wid == 0) {
        float s = fv[cur * KTAG + lane] + trans[STOP_TAG * KTAG + lane];
        unsigned key = ordkey(s);
        unsigned m   = __reduce_max_sync(0xffffffffu, key);
        unsigned bal = __ballot_sync(0xffffffffu, key == m);
        int best = __ffs(bal) - 1;
        float ms = __shfl_sync(0xffffffffu, s, best);
        if (lane == 0) {
            out[0] = ms;
            int tag = best;
            for (int t = T - 1; t >= 0; --t) {
                out[1 + t] = (float)tag;
                tag = bp[t * KTAG + tag];
            }
        }
    }
}

// ---------------- launch ----------------
extern "C" void kernel_launch(void* const* d_in, const int* in_sizes, int n_in,
                              void* d_out, int out_size) {
    (void)in_sizes; (void)n_in; (void)out_size;
    const int*   sent  = (const int*)d_in[0];
    const float* embed = (const float*)d_in[1];
    const float* Wih_f = (const float*)d_in[2];
    const float* Whh_f = (const float*)d_in[3];
    const float* b_f   = (const float*)d_in[4];
    const float* Wih_b = (const float*)d_in[5];
    const float* Whh_b = (const float*)d_in[6];
    const float* b_b   = (const float*)d_in[7];
    const float* W_out = (const float*)d_in[8];
    const float* b_out = (const float*)d_in[9];
    const float* trans = (const float*)d_in[10];
    const float* h0    = (const float*)d_in[11];
    const float* c0    = (const float*)d_in[12];
    float* out = (float*)d_out;

    size_t fsm = (size_t)(HID * 33 + 8 * HID) * sizeof(float);          // ~84 KB
    size_t vsm = (size_t)(T * KTAG) + 2 * KTAG * sizeof(float) + 16;    // ~131.3 KB
    cudaFuncSetAttribute(feats_kernel,   cudaFuncAttributeMaxDynamicSharedMemorySize, (int)fsm);
    cudaFuncSetAttribute(viterbi_kernel, cudaFuncAttributeMaxDynamicSharedMemorySize, (int)vsm);

    gather_kernel<<<T, 128>>>(sent, embed);
    gemm_zx_kernel<<<dim3(T / 32, 8, 2), 256>>>(Wih_f, b_f, Wih_b, b_b);
    lstm_kernel<<<16, 256>>>(Whh_f, Whh_b, h0, c0);
    feats_kernel<<<T / 8, 256, fsm>>>(W_out, b_out);
    viterbi_kernel<<<1, 1024, vsm>>>(trans, out);
}

// round 7
// speedup vs baseline: 1.6461x; 1.5226x over previous
#include <cuda_runtime.h>
#include <cstdint>

#define T     4096
#define E     300
#define HID   512
#define H2    256
#define KTAG  32
#define START_TAG 30
#define STOP_TAG  31
#define NEGV  -10000.0f

// ---------------- scratch (static __device__, no allocations) ----------------
__device__ float g_zx[2][T * 1024];        // Wih@x + b, permuted per-cluster layout
__device__ float g_hs[2][T * H2];          // h sequences
__device__ float g_feats[T * KTAG];        // emission features

// ---------------- helpers ----------------
__device__ __forceinline__ unsigned smem_u32(const void* p) {
    return (unsigned)__cvta_generic_to_shared(p);
}
__device__ __forceinline__ unsigned long long ffma2(unsigned long long a,
                                                    unsigned long long b,
                                                    unsigned long long c) {
    unsigned long long d;
    asm("fma.rn.f32x2 %0, %1, %2, %3;" : "=l"(d) : "l"(a), "l"(b), "l"(c));
    return d;
}
__device__ __forceinline__ float2 ull2f2(unsigned long long v) {
    float2 f;
    f.x = __uint_as_float((unsigned)(v & 0xffffffffull));
    f.y = __uint_as_float((unsigned)(v >> 32));
    return f;
}
__device__ __forceinline__ float sigf(float x) {
    return __fdividef(1.f, 1.f + __expf(-x));
}
__device__ __forceinline__ float tanhf_fast(float x) {
    return 1.f - __fdividef(2.f, 1.f + __expf(2.f * x));
}
__device__ __forceinline__ unsigned ordkey(float x) {
    unsigned b = __float_as_uint(x);
    return ((int)b) >= 0 ? (b | 0x80000000u) : ~b;
}

// ---------------- phase 1: input GEMM (embedding gather fused into xs load) ----------------
__global__ void gemm_zx_kernel(const int* __restrict__ sent,
                               const float* __restrict__ embed,
                               const float* __restrict__ Wf, const float* __restrict__ bf,
                               const float* __restrict__ Wb, const float* __restrict__ bb) {
    __shared__ float xs[32][33];
    __shared__ float ws[128][33];
    int dir = blockIdx.z;
    const float* W = dir ? Wb : Wf;
    const float* B = dir ? bb : bf;
    int t0 = blockIdx.x * 32, r0 = blockIdx.y * 128;
    int tid = threadIdx.x;
    int tq = tid & 7, rq = tid >> 3;

    float acc[4][4];
#pragma unroll
    for (int i = 0; i < 4; i++)
#pragma unroll
        for (int j = 0; j < 4; j++) acc[i][j] = 0.f;

    for (int k0 = 0; k0 < E; k0 += 32) {
        for (int idx = tid; idx < 32 * 32; idx += 256) {
            int tt = idx >> 5, e = idx & 31;
            int k = k0 + e;
            int row = sent[t0 + tt];
            xs[tt][e] = (k < E) ? embed[(size_t)row * E + k] : 0.f;
        }
        for (int idx = tid; idx < 128 * 32; idx += 256) {
            int rr = idx >> 5, e = idx & 31;
            int k = k0 + e;
            ws[rr][e] = (k < E) ? W[(r0 + rr) * E + k] : 0.f;
        }
        __syncthreads();
#pragma unroll
        for (int e = 0; e < 32; e++) {
            float a[4], b4[4];
#pragma unroll
            for (int i = 0; i < 4; i++) a[i] = xs[4 * tq + i][e];
#pragma unroll
            for (int j = 0; j < 4; j++) b4[j] = ws[4 * rq + j][e];
#pragma unroll
            for (int i = 0; i < 4; i++)
#pragma unroll
                for (int j = 0; j < 4; j++) acc[i][j] = fmaf(a[i], b4[j], acc[i][j]);
        }
        __syncthreads();
    }
#pragma unroll
    for (int i = 0; i < 4; i++)
#pragma unroll
        for (int j = 0; j < 4; j++) {
            int t  = t0 + 4 * tq + i;
            int zr = r0 + 4 * rq + j;
            int g = zr >> 8, c = (zr >> 5) & 7, jj = zr & 31;
            int pos = c * 128 + g * 32 + jj;   // per-cluster-CTA contiguous layout
            g_zx[dir][t * 1024 + pos] = acc[i][j] + B[zr];
        }
}

// ---------------- phase 2: recurrent LSTM, cluster of 8 CTAs per direction ----------------
// R3-proven structure (q=tid>>6 broadcast LDS, smem partials, scalar DSMEM
// broadcast, adjacent cluster.arrive/wait). Only delta: zbuf stage + 2nd
// __syncthreads removed — activation warp sums partials directly; zx loaded
// by the activation warp at top of step (overlaps FFMA loop, as in R3).
__global__ void __cluster_dims__(8, 1, 1) __launch_bounds__(256, 1)
lstm_kernel(const float* __restrict__ Whh_f, const float* __restrict__ Whh_b,
            const float* __restrict__ h0, const float* __restrict__ c0) {
    __shared__ __align__(16) float hbuf[2][H2];
    __shared__ float partials[4][128];

    unsigned crank;
    asm("mov.u32 %0, %%cluster_ctarank;" : "=r"(crank));
    int dir = blockIdx.x >> 3;
    const float* Whh = dir ? Whh_b : Whh_f;
    int tid = threadIdx.x;
    int q = tid >> 6;   // column chunk 0..3 (cols 64q..64q+63)
    int p = tid & 63;   // row pair -> local rows 2p, 2p+1
    int l0 = 2 * p, l1 = 2 * p + 1;
    int zr0 = 256 * (l0 >> 5) + 32 * (int)crank + (l0 & 31);
    int zr1 = 256 * (l1 >> 5) + 32 * (int)crank + (l1 & 31);

    // weights resident in registers: 64 floats per row -> 32 f32x2 carriers each
    unsigned long long wA[32], wB[32];
    {
        const ulonglong2* pa = reinterpret_cast<const ulonglong2*>(Whh + (size_t)zr0 * 256 + 64 * q);
        const ulonglong2* pb = reinterpret_cast<const ulonglong2*>(Whh + (size_t)zr1 * 256 + 64 * q);
#pragma unroll
        for (int k = 0; k < 16; k++) {
            ulonglong2 va = pa[k];
            wA[2 * k] = va.x; wA[2 * k + 1] = va.y;
            ulonglong2 vb = pb[k];
            wB[2 * k] = vb.x; wB[2 * k + 1] = vb.y;
        }
    }

    for (int i = tid; i < H2; i += 256) hbuf[0][i] = h0[dir * H2 + i];
    float creg = 0.f;
    if (tid < 32) creg = c0[dir * H2 + 32 * crank + tid];
    __syncthreads();
    asm volatile("barrier.cluster.arrive.aligned;" ::: "memory");
    asm volatile("barrier.cluster.wait.aligned;" ::: "memory");

    int cur = 0;
    for (int s = 0; s < T; s++) {
        int t = dir ? (T - 1 - s) : s;

        // zx for this step, loaded by activation warp; overlaps the FFMA loop
        float zx0 = 0.f, zx1 = 0.f, zx2 = 0.f, zx3 = 0.f;
        if (tid < 32) {
            const float* zp = &g_zx[dir][t * 1024 + (int)crank * 128 + tid];
            zx0 = zp[0]; zx1 = zp[32]; zx2 = zp[64]; zx3 = zp[96];
        }

        unsigned long long a0 = 0, a1 = 0, b0 = 0, b1 = 0;
        const ulonglong2* hp = reinterpret_cast<const ulonglong2*>(&hbuf[cur][64 * q]);
#pragma unroll
        for (int k = 0; k < 16; k++) {
            ulonglong2 h2 = hp[k];                 // broadcast LDS.128 (all lanes same addr)
            a0 = ffma2(wA[2 * k],     h2.x, a0);
            a1 = ffma2(wA[2 * k + 1], h2.y, a1);
            b0 = ffma2(wB[2 * k],     h2.x, b0);
            b1 = ffma2(wB[2 * k + 1], h2.y, b1);
        }
        float2 fa0 = ull2f2(a0), fa1 = ull2f2(a1), fb0 = ull2f2(b0), fb1 = ull2f2(b1);
        partials[q][l0] = (fa0.x + fa0.y) + (fa1.x + fa1.y);
        partials[q][l1] = (fb0.x + fb0.y) + (fb1.x + fb1.y);
        __syncthreads();

        int nxt = cur ^ 1;
        if (tid < 32) {
            float zi = partials[0][tid]      + partials[1][tid]      + partials[2][tid]      + partials[3][tid]      + zx0;
            float zf = partials[0][32 + tid] + partials[1][32 + tid] + partials[2][32 + tid] + partials[3][32 + tid] + zx1;
            float zg = partials[0][64 + tid] + partials[1][64 + tid] + partials[2][64 + tid] + partials[3][64 + tid] + zx2;
            float zo = partials[0][96 + tid] + partials[1][96 + tid] + partials[2][96 + tid] + partials[3][96 + tid] + zx3;
            float si = sigf(zi), sf = sigf(zf), so = sigf(zo);
            creg = sf * creg + si * tanhf_fast(zg);
            float hv = so * tanhf_fast(creg);
            g_hs[dir][t * H2 + 32 * (int)crank + tid] = hv;
            unsigned loff = smem_u32(&hbuf[nxt][32 * (int)crank + tid]);
#pragma unroll
            for (int r = 0; r < 8; r++) {
                unsigned raddr;
                asm("mapa.shared::cluster.u32 %0, %1, %2;" : "=r"(raddr) : "r"(loff), "r"(r));
                asm volatile("st.shared::cluster.f32 [%0], %1;" :: "r"(raddr), "f"(hv) : "memory");
            }
        }
        asm volatile("barrier.cluster.arrive.aligned;" ::: "memory");
        asm volatile("barrier.cluster.wait.aligned;" ::: "memory");
        cur ^= 1;
    }
}

// ---------------- phase 3: emission features feats = [hf|hb] @ W_out^T + b_out ----------------
__global__ void feats_kernel(const float* __restrict__ Wout, const float* __restrict__ bout) {
    extern __shared__ float sm3[];
    float* wt  = sm3;              // [512][33] transposed, padded
    float* hsm = sm3 + HID * 33;   // [8][512]
    int tid = threadIdx.x;
    for (int idx = tid; idx < KTAG * HID; idx += 256) {
        int k = idx >> 9, d = idx & 511;
        wt[d * 33 + k] = Wout[idx];
    }
    int t0 = blockIdx.x * 8;
    for (int idx = tid; idx < 8 * HID; idx += 256) {
        int tt = idx >> 9, d = idx & 511;
        hsm[tt * HID + d] = (d < H2) ? g_hs[0][(t0 + tt) * H2 + d]
                                     : g_hs[1][(t0 + tt) * H2 + d - H2];
    }
    __syncthreads();
    int k = tid & 31, tt = tid >> 5;
    float acc = bout[k];
#pragma unroll 8
    for (int d = 0; d < HID; d++)
        acc = fmaf(hsm[tt * HID + d], wt[d * 33 + k], acc);
    g_feats[(t0 + tt) * KTAG + k] = acc;
}

// ---------------- phase 4: Viterbi forward + backtrace ----------------
__global__ void viterbi_kernel(const float* __restrict__ trans, float* __restrict__ out) {
    extern __shared__ char sm4[];
    unsigned char* bp = (unsigned char*)sm4;        // [T][32]
    float* fv = (float*)(sm4 + T * KTAG);           // [2][32]
    int tid = threadIdx.x, wid = tid >> 5, lane = tid & 31;
    float tr = trans[wid * KTAG + lane];
    if (tid < KTAG) fv[tid] = (tid == START_TAG) ? 0.f : NEGV;
    __syncthreads();

    int cur = 0;
    float feat = g_feats[wid];  // t = 0, row wid (broadcast load)
    for (int t = 0; t < T; t++) {
        float s = fv[cur * KTAG + lane] + tr;
        float fn = (t + 1 < T) ? g_feats[(t + 1) * KTAG + wid] : 0.f;  // prefetch
        unsigned key = ordkey(s);
        unsigned m   = __reduce_max_sync(0xffffffffu, key);
        unsigned bal = __ballot_sync(0xffffffffu, key == m);
        int js = __ffs(bal) - 1;                    // first index -> matches jnp.argmax
        if (lane == js) {
            fv[(cur ^ 1) * KTAG + wid] = s + feat;
            bp[t * KTAG + wid] = (unsigned char)js;
        }
        feat = fn;
        cur ^= 1;
        __syncthreads();
    }
    if (wid == 0) {
        float s = fv[cur * KTAG + lane] + trans[STOP_TAG * KTAG + lane];
        unsigned key = ordkey(s);
        unsigned m   = __reduce_max_sync(0xffffffffu, key);
        unsigned bal = __ballot_sync(0xffffffffu, key == m);
        int best = __ffs(bal) - 1;
        float ms = __shfl_sync(0xffffffffu, s, best);
        if (lane == 0) {
            out[0] = ms;
            int tag = best;
            for (int t = T - 1; t >= 0; --t) {
                out[1 + t] = (float)tag;
                tag = bp[t * KTAG + tag];
            }
        }
    }
}

// ---------------- launch ----------------
extern "C" void kernel_launch(void* const* d_in, const int* in_sizes, int n_in,
                              void* d_out, int out_size) {
    (void)in_sizes; (void)n_in; (void)out_size;
    const int*   sent  = (const int*)d_in[0];
    const float* embed = (const float*)d_in[1];
    const float* Wih_f = (const float*)d_in[2];
    const float* Whh_f = (const float*)d_in[3];
    const float* b_f   = (const float*)d_in[4];
    const float* Wih_b = (const float*)d_in[5];
    const float* Whh_b = (const float*)d_in[6];
    const float* b_b   = (const float*)d_in[7];
    const float* W_out = (const float*)d_in[8];
    const float* b_out = (const float*)d_in[9];
    const float* trans = (const float*)d_in[10];
    const float* h0    = (const float*)d_in[11];
    const float* c0    = (const float*)d_in[12];
    float* out = (float*)d_out;

    size_t fsm = (size_t)(HID * 33 + 8 * HID) * sizeof(float);          // ~84 KB
    size_t vsm = (size_t)(T * KTAG) + 2 * KTAG * sizeof(float) + 16;    // ~131.3 KB
    cudaFuncSetAttribute(feats_kernel,   cudaFuncAttributeMaxDynamicSharedMemorySize, (int)fsm);
    cudaFuncSetAttribute(viterbi_kernel, cudaFuncAttributeMaxDynamicSharedMemorySize, (int)vsm);

    gemm_zx_kernel<<<dim3(T / 32, 8, 2), 256>>>(sent, embed, Wih_f, b_f, Wih_b, b_b);
    lstm_kernel<<<16, 256>>>(Whh_f, Whh_b, h0, c0);
    feats_kernel<<<T / 8, 256, fsm>>>(W_out, b_out);
    viterbi_kernel<<<1, 1024, vsm>>>(trans, out);
}